// round 14
// baseline (speedup 1.0000x reference)
#include <cuda_runtime.h>

// GyroLoss forward — R10 compute (BCH-8 + quat epilogue, 262144 threads) with
// contention-free reduction: per-block partials to dedicated slots (plain STG),
// uint ticket, last block reduces partials from L2. No FP64 atomics anywhere.

#define DT_F 0.01f
#define HUBER_F 0.005f
#define NPER4 2048
#define NPER5 1024
#define N0 5
#define TPB 256
#define MAXBLOCKS 4096

__device__ float g_part4[MAXBLOCKS];
__device__ float g_part5[MAXBLOCKS];
__device__ unsigned int g_count = 0u;

__device__ __forceinline__ void qmul(const float a[4], const float b[4], float c[4]) {
    c[0] = a[0]*b[0] - a[1]*b[1] - a[2]*b[2] - a[3]*b[3];
    c[1] = a[0]*b[1] + a[1]*b[0] + a[2]*b[3] - a[3]*b[2];
    c[2] = a[0]*b[2] - a[1]*b[3] + a[2]*b[0] + a[3]*b[1];
    c[3] = a[0]*b[3] + a[1]*b[2] - a[2]*b[1] + a[3]*b[0];
}

// c = conj(a) ⊗ b
__device__ __forceinline__ void qcmul(const float a[4], const float b[4], float c[4]) {
    c[0] = a[0]*b[0] + a[1]*b[1] + a[2]*b[2] + a[3]*b[3];
    c[1] = a[0]*b[1] - a[1]*b[0] - a[2]*b[3] + a[3]*b[2];
    c[2] = a[0]*b[2] + a[1]*b[3] - a[2]*b[0] - a[3]*b[1];
    c[3] = a[0]*b[3] - a[1]*b[2] + a[2]*b[1] - a[3]*b[0];
}

__device__ __forceinline__ void qexp_phi_small(float x, float y, float z, float q[4]) {
    float sq = x*x + y*y + z*z;
    float hq = 0.25f * sq;
    q[0] = 1.0f + hq * (-0.5f + hq * (1.0f / 24.0f));
    float sf = 0.5f * (1.0f + hq * (-(1.0f / 6.0f) + hq * (1.0f / 120.0f)));
    q[1] = sf * x; q[2] = sf * y; q[3] = sf * z;
}

__device__ __forceinline__ void qexp_full(float x, float y, float z, float q[4]) {
    float sq = x*x + y*y + z*z;
    float a = sq * __frsqrt_rn(fmaxf(sq, 1e-16f));
    float h = 0.5f * a;
    float sh = __sinf(h), ch = __cosf(h);
    float sf = __fdividef(sh, fmaxf(a, 1e-8f));
    q[0] = ch; q[1] = sf * x; q[2] = sf * y; q[3] = sf * z;
}

__device__ __forceinline__ float fast_atan01(float x) {
    float t = x * x;
    float p = -0.0117212f;
    p = fmaf(p, t,  0.05265332f);
    p = fmaf(p, t, -0.11643287f);
    p = fmaf(p, t,  0.19354346f);
    p = fmaf(p, t, -0.33262347f);
    p = fmaf(p, t,  0.99997726f);
    return x * p;
}

__device__ __forceinline__ float huber3_qlog(const float q[4]) {
    float w = q[0], x = q[1], y = q[2], z = q[3];
    float sg = (w < 0.0f) ? -1.0f : 1.0f;
    w *= sg; x *= sg; y *= sg; z *= sg;
    float nv2 = x*x + y*y + z*z;
    float nv = nv2 * __frsqrt_rn(fmaxf(nv2, 1e-24f));
    float lo = fminf(nv, w), hi = fmaxf(nv, w);
    float at = fast_atan01(__fdividef(lo, hi));
    float th = 2.0f * ((nv <= w) ? at : (1.57079632679f - at));
    float f = __fdividef(th, fmaxf(nv, 1e-20f)) * (1.0f / HUBER_F);
    float acc = 0.0f;
#pragma unroll
    for (int t = 0; t < 3; t++) {
        float zz = f * ((t == 0) ? x : (t == 1) ? y : z);
        float az = fabsf(zz);
        acc += (az < 1.0f) ? (0.5f * zz * zz) : (az - 0.5f);
    }
    return acc;
}

// BCH suffix-scan step (reverse time order): C += w x S; S += w
__device__ __forceinline__ void bch_step(float wx, float wy, float wz,
                                         float S[3], float C[3]) {
    C[0] = fmaf(wy, S[2], fmaf(-wz, S[1], C[0]));
    C[1] = fmaf(wz, S[0], fmaf(-wx, S[2], C[1]));
    C[2] = fmaf(wx, S[1], fmaf(-wy, S[0], C[2]));
    S[0] += wx; S[1] += wy; S[2] += wz;
}

__global__ void __launch_bounds__(TPB)
gyro_main_kernel(const float* __restrict__ xs, const float* __restrict__ hx,
                 float* __restrict__ out, int cnt4, int cnt5) {
    int t = blockIdx.x * TPB + threadIdx.x;   // half-group (8 increments)
    int lane = threadIdx.x & 31;

    // --- load 8 increments (24 floats = 6 float4) + xs, front-batched ---
    const float4* hp = reinterpret_cast<const float4*>(hx) + (size_t)t * 6;
    float4 f0 = hp[0], f1 = hp[1], f2 = hp[2], f3 = hp[3], f4 = hp[4], f5 = hp[5];
    float4 xv = *reinterpret_cast<const float4*>(xs + (size_t)(t >> 1) * 48);

    // --- BCH-2 suffix scan over 8 raw increments (reverse time order) ---
    float S[3] = {0.0f, 0.0f, 0.0f};
    float C[3] = {0.0f, 0.0f, 0.0f};
    bch_step(f5.y, f5.z, f5.w, S, C);   // incr 7
    bch_step(f4.z, f4.w, f5.x, S, C);   // incr 6
    bch_step(f3.w, f4.x, f4.y, S, C);   // incr 5
    bch_step(f3.x, f3.y, f3.z, S, C);   // incr 4
    bch_step(f2.y, f2.z, f2.w, S, C);   // incr 3
    bch_step(f1.z, f1.w, f2.x, S, C);   // incr 2
    bch_step(f0.w, f1.x, f1.y, S, C);   // incr 1
    bch_step(f0.x, f0.y, f0.z, S, C);   // incr 0
    float px = fmaf(0.5f * DT_F * DT_F, C[0], DT_F * S[0]);
    float py = fmaf(0.5f * DT_F * DT_F, C[1], DT_F * S[1]);
    float pz = fmaf(0.5f * DT_F * DT_F, C[2], DT_F * S[2]);
    float q8[4];
    qexp_phi_small(px, py, pz, q8);

    // --- 16-group: even lane combines with odd partner ---
    float q16[4];
    {
        float qp[4];
#pragma unroll
        for (int k = 0; k < 4; k++)
            qp[k] = __shfl_down_sync(0xFFFFFFFFu, q8[k], 1);
        qmul(q8, qp, q16);                           // valid on even lanes
    }

    // --- ground-truth quat (pair lanes broadcast same float4) ---
    float qR[4];
    qexp_full(xv.x, xv.y, xv.z, qR);

    // --- level-5 operands: gather within lane quad ---
    int lb = lane & ~3;
    float q32[4], qR32[4];
    {
        float qa[4], qb[4], ra[4];
#pragma unroll
        for (int k = 0; k < 4; k++) {
            qa[k] = __shfl_sync(0xFFFFFFFFu, q16[k], lb);
            qb[k] = __shfl_sync(0xFFFFFFFFu, q16[k], lb | 2);
            ra[k] = __shfl_sync(0xFFFFFFFFu, qR[k],  lb);
        }
        qmul(qa, qb, q32);                           // used on lane ≡3
        qmul(ra, qR, qR32);                          // lane3's own qR = group 2j+1
    }

    // --- converged relative-rotation log + huber ---
    int m = t & 3;
    float relA[4], relB[4], rel[4];
    qcmul(q16, qR, relA);                            // level-4 (even lanes)
    qcmul(q32, qR32, relB);                          // level-5 (lane ≡3)
#pragma unroll
    for (int k = 0; k < 4; k++) rel[k] = (m == 3) ? relB[k] : relA[k];
    float h = huber3_qlog(rel);

    float s4 = 0.0f, s5 = 0.0f;
    if ((m & 1) == 0) {                              // lanes ≡0,2: level-4
        int i4 = (t >> 1) & (NPER4 - 1);
        if (i4 >= N0) s4 = h;
    } else if (m == 3) {                             // lane ≡3: level-5
        int j5 = (t >> 2) & (NPER5 - 1);
        if (j5 >= N0) s5 = h;
    }

    // --- block reduction ---
#pragma unroll
    for (int off = 16; off > 0; off >>= 1) {
        s4 += __shfl_down_sync(0xFFFFFFFFu, s4, off);
        s5 += __shfl_down_sync(0xFFFFFFFFu, s5, off);
    }
    __shared__ float sh4[TPB / 32];
    __shared__ float sh5[TPB / 32];
    __shared__ bool last_block;
    int warp = threadIdx.x >> 5;
    if (lane == 0) { sh4[warp] = s4; sh5[warp] = s5; }
    __syncthreads();

    if (threadIdx.x == 0) {
        float b4 = 0.0f, b5 = 0.0f;
#pragma unroll
        for (int w = 0; w < TPB / 32; w++) { b4 += sh4[w]; b5 += sh5[w]; }
        // contention-free partial store (own slot)
        g_part4[blockIdx.x] = b4;
        g_part5[blockIdx.x] = b5;
        __threadfence();
        unsigned int ticket = atomicAdd(&g_count, 1u);
        last_block = (ticket == gridDim.x - 1);
    }
    __syncthreads();

    if (last_block) {
        // whole last block reduces all partials straight from L2
        float r4 = 0.0f, r5 = 0.0f;
        for (int i = threadIdx.x; i < gridDim.x; i += TPB) {
            r4 += __ldcg(&g_part4[i]);
            r5 += __ldcg(&g_part5[i]);
        }
#pragma unroll
        for (int off = 16; off > 0; off >>= 1) {
            r4 += __shfl_down_sync(0xFFFFFFFFu, r4, off);
            r5 += __shfl_down_sync(0xFFFFFFFFu, r5, off);
        }
        if (lane == 0) { sh4[warp] = r4; sh5[warp] = r5; }
        __syncthreads();
        if (threadIdx.x == 0) {
            double t4 = 0.0, t5 = 0.0;
#pragma unroll
            for (int w = 0; w < TPB / 32; w++) { t4 += (double)sh4[w]; t5 += (double)sh5[w]; }
            // loss = W*HUBER^2 * (mean4 + 0.5*mean5); W*HUBER^2 = 25
            double loss = 25.0 * (t4 / (double)cnt4 + 0.5 * t5 / (double)cnt5);
            out[0] = (float)loss;
            g_count = 0u;                            // reset for graph replay
        }
    }
}

extern "C" void kernel_launch(void* const* d_in, const int* in_sizes, int n_in,
                              void* d_out, int out_size) {
    const float* xs = (const float*)d_in[0];
    // d_in[1] = dp, unused by forward
    const float* hx = (const float*)d_in[2];

    int total = in_sizes[2];              // N*T*3 = 6291456
    int halves = total / 24;              // 262144 threads (8 increments each)
    int groups = total / 48;              // 131072
    int nbatch = 64;
    int g4_per_batch = groups / nbatch;   // 2048
    int g5_per_batch = g4_per_batch / 2;  // 1024
    int cnt4 = nbatch * (g4_per_batch - N0) * 3;   // 392256
    int cnt5 = nbatch * (g5_per_batch - N0) * 3;   // 195648

    gyro_main_kernel<<<halves / TPB, TPB>>>(xs, hx, (float*)d_out, cnt4, cnt5);
}

// round 15
// speedup vs baseline: 1.0226x; 1.0226x over previous
#include <cuda_runtime.h>

// GyroLoss forward — R10 math (BCH-8 + quat epilogue) software-pipelined:
// 2 half-groups per thread (131072 threads), all loads front-issued so
// iteration-0 compute hides iteration-1 memory latency. R10 reduction.

#define DT_F 0.01f
#define HUBER_F 0.005f
#define NPER4 2048
#define NPER5 1024
#define N0 5
#define TPB 256
#define HALVES_TOTAL 262144
#define HALF_STRIDE 131072

__device__ double g_sum4 = 0.0;
__device__ double g_sum5 = 0.0;
__device__ unsigned int g_count = 0u;

__device__ __forceinline__ void qmul(const float a[4], const float b[4], float c[4]) {
    c[0] = a[0]*b[0] - a[1]*b[1] - a[2]*b[2] - a[3]*b[3];
    c[1] = a[0]*b[1] + a[1]*b[0] + a[2]*b[3] - a[3]*b[2];
    c[2] = a[0]*b[2] - a[1]*b[3] + a[2]*b[0] + a[3]*b[1];
    c[3] = a[0]*b[3] + a[1]*b[2] - a[2]*b[1] + a[3]*b[0];
}

// c = conj(a) ⊗ b
__device__ __forceinline__ void qcmul(const float a[4], const float b[4], float c[4]) {
    c[0] = a[0]*b[0] + a[1]*b[1] + a[2]*b[2] + a[3]*b[3];
    c[1] = a[0]*b[1] - a[1]*b[0] - a[2]*b[3] + a[3]*b[2];
    c[2] = a[0]*b[2] + a[1]*b[3] - a[2]*b[0] - a[3]*b[1];
    c[3] = a[0]*b[3] - a[1]*b[2] + a[2]*b[1] - a[3]*b[0];
}

__device__ __forceinline__ void qexp_phi_small(float x, float y, float z, float q[4]) {
    float sq = x*x + y*y + z*z;
    float hq = 0.25f * sq;
    q[0] = 1.0f + hq * (-0.5f + hq * (1.0f / 24.0f));
    float sf = 0.5f * (1.0f + hq * (-(1.0f / 6.0f) + hq * (1.0f / 120.0f)));
    q[1] = sf * x; q[2] = sf * y; q[3] = sf * z;
}

__device__ __forceinline__ void qexp_full(float x, float y, float z, float q[4]) {
    float sq = x*x + y*y + z*z;
    float a = sq * __frsqrt_rn(fmaxf(sq, 1e-16f));
    float h = 0.5f * a;
    float sh = __sinf(h), ch = __cosf(h);
    float sf = __fdividef(sh, fmaxf(a, 1e-8f));
    q[0] = ch; q[1] = sf * x; q[2] = sf * y; q[3] = sf * z;
}

__device__ __forceinline__ float fast_atan01(float x) {
    float t = x * x;
    float p = -0.0117212f;
    p = fmaf(p, t,  0.05265332f);
    p = fmaf(p, t, -0.11643287f);
    p = fmaf(p, t,  0.19354346f);
    p = fmaf(p, t, -0.33262347f);
    p = fmaf(p, t,  0.99997726f);
    return x * p;
}

__device__ __forceinline__ float huber3_qlog(const float q[4]) {
    float w = q[0], x = q[1], y = q[2], z = q[3];
    float sg = (w < 0.0f) ? -1.0f : 1.0f;
    w *= sg; x *= sg; y *= sg; z *= sg;
    float nv2 = x*x + y*y + z*z;
    float nv = nv2 * __frsqrt_rn(fmaxf(nv2, 1e-24f));
    float lo = fminf(nv, w), hi = fmaxf(nv, w);
    float at = fast_atan01(__fdividef(lo, hi));
    float th = 2.0f * ((nv <= w) ? at : (1.57079632679f - at));
    float f = __fdividef(th, fmaxf(nv, 1e-20f)) * (1.0f / HUBER_F);
    float acc = 0.0f;
#pragma unroll
    for (int t = 0; t < 3; t++) {
        float zz = f * ((t == 0) ? x : (t == 1) ? y : z);
        float az = fabsf(zz);
        acc += (az < 1.0f) ? (0.5f * zz * zz) : (az - 0.5f);
    }
    return acc;
}

// BCH suffix-scan step (reverse time order): C += w x S; S += w
__device__ __forceinline__ void bch_step(float wx, float wy, float wz,
                                         float S[3], float C[3]) {
    C[0] = fmaf(wy, S[2], fmaf(-wz, S[1], C[0]));
    C[1] = fmaf(wz, S[0], fmaf(-wx, S[2], C[1]));
    C[2] = fmaf(wx, S[1], fmaf(-wy, S[0], C[2]));
    S[0] += wx; S[1] += wy; S[2] += wz;
}

// one half-group's full compute: accumulates s4/s5 for this thread's role
__device__ __forceinline__ void compute_half(int t, int lane,
        float4 f0, float4 f1, float4 f2, float4 f3, float4 f4, float4 f5,
        float4 xv, float& s4, float& s5) {
    // BCH-2 suffix scan over 8 raw increments (reverse time order)
    float S[3], C[3];
    S[0] = f5.y; S[1] = f5.z; S[2] = f5.w;           // incr 7
    C[0] = 0.0f; C[1] = 0.0f; C[2] = 0.0f;
    bch_step(f4.z, f4.w, f5.x, S, C);   // incr 6
    bch_step(f3.w, f4.x, f4.y, S, C);   // incr 5
    bch_step(f3.x, f3.y, f3.z, S, C);   // incr 4
    bch_step(f2.y, f2.z, f2.w, S, C);   // incr 3
    bch_step(f1.z, f1.w, f2.x, S, C);   // incr 2
    bch_step(f0.w, f1.x, f1.y, S, C);   // incr 1
    bch_step(f0.x, f0.y, f0.z, S, C);   // incr 0
    float q8[4];
    qexp_phi_small(fmaf(0.5f * DT_F * DT_F, C[0], DT_F * S[0]),
                   fmaf(0.5f * DT_F * DT_F, C[1], DT_F * S[1]),
                   fmaf(0.5f * DT_F * DT_F, C[2], DT_F * S[2]), q8);

    // 16-group: even lane combines with odd partner
    float q16[4];
    {
        float qp[4];
#pragma unroll
        for (int k = 0; k < 4; k++)
            qp[k] = __shfl_down_sync(0xFFFFFFFFu, q8[k], 1);
        qmul(q8, qp, q16);                           // valid on even lanes
    }

    // ground-truth quat (pair lanes broadcast same float4)
    float qR[4];
    qexp_full(xv.x, xv.y, xv.z, qR);

    // level-5 operands: gather within lane quad
    int lb = lane & ~3;
    float q32[4], qR32[4];
    {
        float qa[4], qb[4], ra[4];
#pragma unroll
        for (int k = 0; k < 4; k++) {
            qa[k] = __shfl_sync(0xFFFFFFFFu, q16[k], lb);
            qb[k] = __shfl_sync(0xFFFFFFFFu, q16[k], lb | 2);
            ra[k] = __shfl_sync(0xFFFFFFFFu, qR[k],  lb);
        }
        qmul(qa, qb, q32);                           // used on lane ≡3
        qmul(ra, qR, qR32);                          // lane3's own qR = group 2j+1
    }

    // converged relative-rotation log + huber
    int m = t & 3;
    float relA[4], relB[4], rel[4];
    qcmul(q16, qR, relA);                            // level-4 (even lanes)
    qcmul(q32, qR32, relB);                          // level-5 (lane ≡3)
#pragma unroll
    for (int k = 0; k < 4; k++) rel[k] = (m == 3) ? relB[k] : relA[k];
    float h = huber3_qlog(rel);

    if ((m & 1) == 0) {                              // lanes ≡0,2: level-4
        int i4 = (t >> 1) & (NPER4 - 1);
        if (i4 >= N0) s4 += h;
    } else if (m == 3) {                             // lane ≡3: level-5
        int j5 = (t >> 2) & (NPER5 - 1);
        if (j5 >= N0) s5 += h;
    }
}

__global__ void __launch_bounds__(TPB)
gyro_main_kernel(const float* __restrict__ xs, const float* __restrict__ hx,
                 float* __restrict__ out, int cnt4, int cnt5) {
    int t0 = blockIdx.x * TPB + threadIdx.x;         // first half-group
    int t1 = t0 + HALF_STRIDE;                       // second half-group
    int lane = threadIdx.x & 31;

    // --- ALL loads front-issued: 12 float4 (hat) + 2 float4 (xs), MLP=14 ---
    const float4* hp0 = reinterpret_cast<const float4*>(hx) + (size_t)t0 * 6;
    const float4* hp1 = reinterpret_cast<const float4*>(hx) + (size_t)t1 * 6;
    float4 a0 = hp0[0], a1 = hp0[1], a2 = hp0[2], a3 = hp0[3], a4 = hp0[4], a5 = hp0[5];
    float4 b0 = hp1[0], b1 = hp1[1], b2 = hp1[2], b3 = hp1[3], b4 = hp1[4], b5 = hp1[5];
    float4 xv0 = *reinterpret_cast<const float4*>(xs + (size_t)(t0 >> 1) * 48);
    float4 xv1 = *reinterpret_cast<const float4*>(xs + (size_t)(t1 >> 1) * 48);

    float s4 = 0.0f, s5 = 0.0f;
    compute_half(t0, lane, a0, a1, a2, a3, a4, a5, xv0, s4, s5);
    compute_half(t1, lane, b0, b1, b2, b3, b4, b5, xv1, s4, s5);

    // --- reduction (R10 scheme) ---
#pragma unroll
    for (int off = 16; off > 0; off >>= 1) {
        s4 += __shfl_down_sync(0xFFFFFFFFu, s4, off);
        s5 += __shfl_down_sync(0xFFFFFFFFu, s5, off);
    }
    __shared__ float sh4[TPB / 32];
    __shared__ float sh5[TPB / 32];
    int warp = threadIdx.x >> 5;
    if (lane == 0) { sh4[warp] = s4; sh5[warp] = s5; }
    __syncthreads();

    if (threadIdx.x == 0) {
        float p4 = 0.0f, p5 = 0.0f;
#pragma unroll
        for (int w = 0; w < TPB / 32; w++) { p4 += sh4[w]; p5 += sh5[w]; }
        atomicAdd(&g_sum4, (double)p4);
        atomicAdd(&g_sum5, (double)p5);
        __threadfence();
        unsigned int ticket = atomicAdd(&g_count, 1u);
        if (ticket == gridDim.x - 1) {
            double s4t = atomicAdd(&g_sum4, 0.0);
            double s5t = atomicAdd(&g_sum5, 0.0);
            // loss = W*HUBER^2 * (mean4 + 0.5*mean5); W*HUBER^2 = 25
            double loss = 25.0 * (s4t / (double)cnt4 + 0.5 * s5t / (double)cnt5);
            out[0] = (float)loss;
            g_sum4 = 0.0;
            g_sum5 = 0.0;
            __threadfence();
            g_count = 0u;
        }
    }
}

extern "C" void kernel_launch(void* const* d_in, const int* in_sizes, int n_in,
                              void* d_out, int out_size) {
    const float* xs = (const float*)d_in[0];
    // d_in[1] = dp, unused by forward
    const float* hx = (const float*)d_in[2];

    int total = in_sizes[2];              // N*T*3 = 6291456
    int halves = total / 24;              // 262144 half-groups
    int groups = total / 48;              // 131072
    int nbatch = 64;
    int g4_per_batch = groups / nbatch;   // 2048
    int g5_per_batch = g4_per_batch / 2;  // 1024
    int cnt4 = nbatch * (g4_per_batch - N0) * 3;   // 392256
    int cnt5 = nbatch * (g5_per_batch - N0) * 3;   // 195648

    gyro_main_kernel<<<halves / (2 * TPB), TPB>>>(xs, hx, (float*)d_out, cnt4, cnt5);
}